// round 1
// baseline (speedup 1.0000x reference)
#include <cuda_runtime.h>

// Problem dims
#define BATCH 4
#define SEQ   4096
#define DIM   512

// Static scratch (allocation-free, zero-init at module load)
__device__ float g_Q[(size_t)BATCH * SEQ * DIM];
__device__ float g_K[(size_t)BATCH * SEQ * DIM];
__device__ float g_V[(size_t)BATCH * SEQ * DIM];
__device__ float g_P[(size_t)BATCH * SEQ * SEQ];   // scores / probs, 256 MB

// Tiling: 128x128 block tile, BK=16, 256 threads, 8x8 per thread.
#define BM 128
#define BN 128
#define BK 16

// ---------------------------------------------------------------------------
// QKV projection: C[m,n] = sum_k X[m,k] * W[n,k]   (A * B^T, both K-major)
// grid: (DIM/BN=4, (B*S)/BM=128, 3)  z selects {Q,K,V}
// ---------------------------------------------------------------------------
__global__ __launch_bounds__(256) void proj_kernel(
    const float* __restrict__ X,
    const float* __restrict__ WQ,
    const float* __restrict__ WK,
    const float* __restrict__ WV)
{
    const float* W = (blockIdx.z == 0) ? WQ : (blockIdx.z == 1) ? WK : WV;
    float*       C = (blockIdx.z == 0) ? g_Q : (blockIdx.z == 1) ? g_K : g_V;

    __shared__ float As[BK][BM];
    __shared__ float Bs[BK][BN];

    const int tid = threadIdx.x;
    const int tx  = tid & 15;
    const int ty  = tid >> 4;

    const float* Ab = X + (size_t)blockIdx.y * BM * DIM;
    const float* Bb = W + (size_t)blockIdx.x * BN * DIM;

    float acc[8][8];
#pragma unroll
    for (int i = 0; i < 8; i++)
#pragma unroll
        for (int j = 0; j < 8; j++) acc[i][j] = 0.f;

    for (int k0 = 0; k0 < DIM; k0 += BK) {
#pragma unroll
        for (int v = 0; v < 2; v++) {
            int idx = tid + v * 256;          // 0..511
            int row = idx >> 2;               // 0..127
            int c4  = (idx & 3) * 4;          // 0,4,8,12
            float4 a = *(const float4*)(Ab + (size_t)row * DIM + k0 + c4);
            As[c4 + 0][row] = a.x; As[c4 + 1][row] = a.y;
            As[c4 + 2][row] = a.z; As[c4 + 3][row] = a.w;
            float4 b = *(const float4*)(Bb + (size_t)row * DIM + k0 + c4);
            Bs[c4 + 0][row] = b.x; Bs[c4 + 1][row] = b.y;
            Bs[c4 + 2][row] = b.z; Bs[c4 + 3][row] = b.w;
        }
        __syncthreads();
#pragma unroll
        for (int kk = 0; kk < BK; kk++) {
            float a[8], b[8];
            *(float4*)(a)     = *(const float4*)&As[kk][ty * 8];
            *(float4*)(a + 4) = *(const float4*)&As[kk][ty * 8 + 4];
            *(float4*)(b)     = *(const float4*)&Bs[kk][tx * 8];
            *(float4*)(b + 4) = *(const float4*)&Bs[kk][tx * 8 + 4];
#pragma unroll
            for (int i = 0; i < 8; i++)
#pragma unroll
                for (int j = 0; j < 8; j++) acc[i][j] += a[i] * b[j];
        }
        __syncthreads();
    }

    float* Cb = C + (size_t)(blockIdx.y * BM) * DIM + blockIdx.x * BN;
#pragma unroll
    for (int i = 0; i < 8; i++) {
        float* crow = Cb + (size_t)(ty * 8 + i) * DIM + tx * 8;
        *(float4*)(crow)     = *(float4*)&acc[i][0];
        *(float4*)(crow + 4) = *(float4*)&acc[i][4];
    }
}

// ---------------------------------------------------------------------------
// Scores: P[q,k] = scale * sum_d Q[q,d]*K[k,d], causal mask, skip kt>qt tiles.
// grid: (32 kt, 32 qt, 4 b)
// ---------------------------------------------------------------------------
__global__ __launch_bounds__(256) void scores_kernel()
{
    const int kt = blockIdx.x, qt = blockIdx.y, b = blockIdx.z;
    if (kt > qt) return;

    __shared__ float As[BK][BM];
    __shared__ float Bs[BK][BN];

    const int tid = threadIdx.x;
    const int tx  = tid & 15;
    const int ty  = tid >> 4;

    const float* Ab = g_Q + (size_t)b * SEQ * DIM + (size_t)qt * BM * DIM;
    const float* Bb = g_K + (size_t)b * SEQ * DIM + (size_t)kt * BN * DIM;

    float acc[8][8];
#pragma unroll
    for (int i = 0; i < 8; i++)
#pragma unroll
        for (int j = 0; j < 8; j++) acc[i][j] = 0.f;

    for (int k0 = 0; k0 < DIM; k0 += BK) {
#pragma unroll
        for (int v = 0; v < 2; v++) {
            int idx = tid + v * 256;
            int row = idx >> 2;
            int c4  = (idx & 3) * 4;
            float4 a = *(const float4*)(Ab + (size_t)row * DIM + k0 + c4);
            As[c4 + 0][row] = a.x; As[c4 + 1][row] = a.y;
            As[c4 + 2][row] = a.z; As[c4 + 3][row] = a.w;
            float4 bv = *(const float4*)(Bb + (size_t)row * DIM + k0 + c4);
            Bs[c4 + 0][row] = bv.x; Bs[c4 + 1][row] = bv.y;
            Bs[c4 + 2][row] = bv.z; Bs[c4 + 3][row] = bv.w;
        }
        __syncthreads();
#pragma unroll
        for (int kk = 0; kk < BK; kk++) {
            float a[8], bv[8];
            *(float4*)(a)      = *(const float4*)&As[kk][ty * 8];
            *(float4*)(a + 4)  = *(const float4*)&As[kk][ty * 8 + 4];
            *(float4*)(bv)     = *(const float4*)&Bs[kk][tx * 8];
            *(float4*)(bv + 4) = *(const float4*)&Bs[kk][tx * 8 + 4];
#pragma unroll
            for (int i = 0; i < 8; i++)
#pragma unroll
                for (int j = 0; j < 8; j++) acc[i][j] += a[i] * bv[j];
        }
        __syncthreads();
    }

    const float scale = 0.04419417382415922f;  // 1/sqrt(512)
    float* Cb = g_P + (size_t)b * SEQ * SEQ + (size_t)(qt * BM) * SEQ + kt * BN;

    if (kt == qt) {
        // diagonal tile: element-wise causal mask
#pragma unroll
        for (int i = 0; i < 8; i++) {
            int gi = ty * 8 + i;  // local row == (global row - qt*128)
#pragma unroll
            for (int j = 0; j < 8; j++) {
                int gj = tx * 8 + j;
                Cb[(size_t)gi * SEQ + gj] = (gj <= gi) ? acc[i][j] * scale : -1e30f;
            }
        }
    } else {
#pragma unroll
        for (int i = 0; i < 8; i++) {
            float* crow = Cb + (size_t)(ty * 8 + i) * SEQ + tx * 8;
            float4 v0 = make_float4(acc[i][0]*scale, acc[i][1]*scale, acc[i][2]*scale, acc[i][3]*scale);
            float4 v1 = make_float4(acc[i][4]*scale, acc[i][5]*scale, acc[i][6]*scale, acc[i][7]*scale);
            *(float4*)(crow)     = v0;
            *(float4*)(crow + 4) = v1;
        }
    }
}

// ---------------------------------------------------------------------------
// Row softmax over [0, jend) where jend = (qt+1)*128 (masked entries -> 0)
// grid: 16384 blocks (one row), 256 threads
// ---------------------------------------------------------------------------
__global__ __launch_bounds__(256) void softmax_kernel()
{
    const int r = blockIdx.x;
    const int b = r >> 12;         // /4096
    const int i = r & 4095;
    float* row = g_P + (size_t)b * SEQ * SEQ + (size_t)i * SEQ;
    const int jend = ((i >> 7) + 1) << 7;

    const int tid  = threadIdx.x;
    const int lane = tid & 31;
    const int wid  = tid >> 5;
    __shared__ float red[8];

    // 1) max
    float m = -1e30f;
    for (int j = tid; j < jend; j += 256) m = fmaxf(m, row[j]);
#pragma unroll
    for (int o = 16; o > 0; o >>= 1) m = fmaxf(m, __shfl_xor_sync(0xffffffffu, m, o));
    if (lane == 0) red[wid] = m;
    __syncthreads();
    m = red[0];
#pragma unroll
    for (int w = 1; w < 8; w++) m = fmaxf(m, red[w]);
    __syncthreads();

    // 2) sum of exp
    float s = 0.f;
    for (int j = tid; j < jend; j += 256) s += expf(row[j] - m);
#pragma unroll
    for (int o = 16; o > 0; o >>= 1) s += __shfl_xor_sync(0xffffffffu, s, o);
    if (lane == 0) red[wid] = s;
    __syncthreads();
    s = red[0];
#pragma unroll
    for (int w = 1; w < 8; w++) s += red[w];

    // 3) normalize in place
    const float inv = 1.0f / s;
    for (int j = tid; j < jend; j += 256) row[j] = expf(row[j] - m) * inv;
}

// ---------------------------------------------------------------------------
// PV: Out[q,d] = sum_k P[q,k] * V[k,d]   (A * B, B is N-major)
// grid: (DIM/BN=4, 32 qt, 4 b), K-loop bounded by causal extent
// ---------------------------------------------------------------------------
__global__ __launch_bounds__(256) void pv_kernel(float* __restrict__ Out)
{
    const int nt = blockIdx.x, qt = blockIdx.y, b = blockIdx.z;

    __shared__ float As[BK][BM];
    __shared__ float Bs[BK][BN];

    const int tid = threadIdx.x;
    const int tx  = tid & 15;
    const int ty  = tid >> 4;

    const float* Ab = g_P + (size_t)b * SEQ * SEQ + (size_t)qt * BM * SEQ;
    const float* Vb = g_V + (size_t)b * SEQ * DIM;
    const int kmax = (qt + 1) * 128;

    float acc[8][8];
#pragma unroll
    for (int i = 0; i < 8; i++)
#pragma unroll
        for (int j = 0; j < 8; j++) acc[i][j] = 0.f;

    for (int k0 = 0; k0 < kmax; k0 += BK) {
        // A tile: P rows, K contiguous (lda = SEQ)
#pragma unroll
        for (int v = 0; v < 2; v++) {
            int idx = tid + v * 256;
            int row = idx >> 2;
            int c4  = (idx & 3) * 4;
            float4 a = *(const float4*)(Ab + (size_t)row * SEQ + k0 + c4);
            As[c4 + 0][row] = a.x; As[c4 + 1][row] = a.y;
            As[c4 + 2][row] = a.z; As[c4 + 3][row] = a.w;
        }
        // B tile: V rows k0..k0+15, cols nt*128..+127 (N contiguous)
#pragma unroll
        for (int v = 0; v < 2; v++) {
            int idx = tid + v * 256;
            int row = idx >> 5;               // 0..15
            int c   = (idx & 31) * 4;          // 0..124
            *(float4*)&Bs[row][c] =
                *(const float4*)(Vb + (size_t)(k0 + row) * DIM + nt * BN + c);
        }
        __syncthreads();
#pragma unroll
        for (int kk = 0; kk < BK; kk++) {
            float a[8], bv[8];
            *(float4*)(a)      = *(const float4*)&As[kk][ty * 8];
            *(float4*)(a + 4)  = *(const float4*)&As[kk][ty * 8 + 4];
            *(float4*)(bv)     = *(const float4*)&Bs[kk][tx * 8];
            *(float4*)(bv + 4) = *(const float4*)&Bs[kk][tx * 8 + 4];
#pragma unroll
            for (int i = 0; i < 8; i++)
#pragma unroll
                for (int j = 0; j < 8; j++) acc[i][j] += a[i] * bv[j];
        }
        __syncthreads();
    }

    float* Cb = Out + (size_t)b * SEQ * DIM + (size_t)(qt * BM) * DIM + nt * BN;
#pragma unroll
    for (int i = 0; i < 8; i++) {
        float* crow = Cb + (size_t)(ty * 8 + i) * DIM + tx * 8;
        *(float4*)(crow)     = *(float4*)&acc[i][0];
        *(float4*)(crow + 4) = *(float4*)&acc[i][4];
    }
}

// ---------------------------------------------------------------------------
extern "C" void kernel_launch(void* const* d_in, const int* in_sizes, int n_in,
                              void* d_out, int out_size)
{
    const float* x  = (const float*)d_in[0];
    const float* WQ = (const float*)d_in[1];
    const float* WK = (const float*)d_in[2];
    const float* WV = (const float*)d_in[3];
    float* out = (float*)d_out;

    dim3 blk(256);

    dim3 gproj(DIM / BN, (BATCH * SEQ) / BM, 3);      // (4,128,3)
    proj_kernel<<<gproj, blk>>>(x, WQ, WK, WV);

    dim3 gsc(SEQ / BN, SEQ / BM, BATCH);              // (32,32,4)
    scores_kernel<<<gsc, blk>>>();

    softmax_kernel<<<BATCH * SEQ, 256>>>();           // 16384 rows

    dim3 gpv(DIM / BN, SEQ / BM, BATCH);              // (4,32,4)
    pv_kernel<<<gpv, blk>>>(out);
}

// round 4
// speedup vs baseline: 1.9588x; 1.9588x over previous
#include <cuda_runtime.h>
#include <cuda_bf16.h>
#include <cstdint>

#define BATCH 4
#define SEQ   4096
#define DIM   512

#define NSD (4ull*4096ull*512ull)     // 8,388,608
#define NW  (3ull*512ull*512ull)      // 786,432
#define NSS (4ull*4096ull*4096ull)    // 67,108,864

// ---------------- static scratch (allocation-free) ----------------
__device__ __nv_bfloat16 g_Xh[NSD], g_Xl[NSD];
__device__ __nv_bfloat16 g_Wh[NW],  g_Wl[NW];
__device__ __nv_bfloat16 g_Qh[NSD], g_Ql[NSD];
__device__ __nv_bfloat16 g_Kh[NSD], g_Kl[NSD];
__device__ __nv_bfloat16 g_Vh[NSD], g_Vl[NSD];
__device__ __nv_bfloat16 g_VTh[NSD], g_VTl[NSD];
__device__ float         g_P[NSS];
__device__ __nv_bfloat16 g_Ph[NSS], g_Pl[NSS];

// ---------------- PTX helpers (compute_103-baseline ISA only) ----------------
__device__ __forceinline__ uint32_t smem_u32(const void* p) {
    uint32_t a;
    asm("{ .reg .u64 t; cvta.to.shared.u64 t, %1; cvt.u32.u64 %0, t; }" : "=r"(a) : "l"(p));
    return a;
}

__device__ __forceinline__ void cp16(uint32_t s, const void* g) {
    asm volatile("cp.async.cg.shared.global [%0], [%1], 16;" :: "r"(s), "l"(g) : "memory");
}
#define CP_COMMIT() asm volatile("cp.async.commit_group;" ::: "memory")
#define CP_WAIT(n)  asm volatile("cp.async.wait_group %0;" :: "n"(n) : "memory")

__device__ __forceinline__ void ldm4(uint32_t addr, uint32_t r[4]) {
    asm volatile("ldmatrix.sync.aligned.m8n8.x4.shared.b16 {%0,%1,%2,%3}, [%4];"
                 : "=r"(r[0]), "=r"(r[1]), "=r"(r[2]), "=r"(r[3]) : "r"(addr));
}

__device__ __forceinline__ void mma16816(float* c, const uint32_t* a, uint32_t b0, uint32_t b1) {
    asm volatile(
        "mma.sync.aligned.m16n8k16.row.col.f32.bf16.bf16.f32 "
        "{%0,%1,%2,%3}, {%4,%5,%6,%7}, {%8,%9}, {%0,%1,%2,%3};"
        : "+f"(c[0]), "+f"(c[1]), "+f"(c[2]), "+f"(c[3])
        : "r"(a[0]), "r"(a[1]), "r"(a[2]), "r"(a[3]), "r"(b0), "r"(b1));
}

// ---------------- GEMM config ----------------
// CTA tile 128x128, 256 thr = 8 warps (2 M x 4 N), warp tile 64x32.
// K-chunk 32 bf16. SMEM rows padded to 80B -> conflict-free ldmatrix.
#define ROWP     80
#define TILE_B   (128 * ROWP)          // 10240
#define OFF_AH   0
#define OFF_AL   (1 * TILE_B)
#define OFF_BH   (2 * TILE_B)
#define OFF_BL   (3 * TILE_B)
#define STAGE_B  (4 * TILE_B)          // 40960
#define SMEM_ALLOC (2 * STAGE_B)       // 81920

// one 128x32-bf16 tile -> smem (16B chunks, 4 per row)
__device__ __forceinline__ void fill_tile(uint32_t sb, const __nv_bfloat16* __restrict__ src,
                                          int ld, int k0, int tid) {
#pragma unroll
    for (int v = 0; v < 2; ++v) {
        int idx = v * 256 + tid;          // 0..511
        int row = idx >> 2;               // 0..127
        int c16 = idx & 3;                // 0..3
        cp16(sb + row * ROWP + c16 * 16, src + (size_t)row * ld + k0 + c16 * 8);
    }
}

__device__ __forceinline__ void fill_chunk(uint32_t sb,
    const __nv_bfloat16* Ah, const __nv_bfloat16* Al, int lda,
    const __nv_bfloat16* Bh, const __nv_bfloat16* Bl, int ldb,
    int k0, int tid)
{
    fill_tile(sb + OFF_AH, Ah, lda, k0, tid);
    fill_tile(sb + OFF_AL, Al, lda, k0, tid);
    fill_tile(sb + OFF_BH, Bh, ldb, k0, tid);
    fill_tile(sb + OFF_BL, Bl, ldb, k0, tid);
}

// bf16x3 mainloop: acc(128x128 fp32) = (Ah+Al)(Bh+Bl)^T, dropping Al*Bl.
// acc[mf][nf][4] per thread (warp 64x32 tile, m16n8 fragments).
__device__ __forceinline__ void gemm_bf16x3(
    const __nv_bfloat16* __restrict__ Ah, const __nv_bfloat16* __restrict__ Al, int lda,
    const __nv_bfloat16* __restrict__ Bh, const __nv_bfloat16* __restrict__ Bl, int ldb,
    int ktotal, float acc[4][4][4])
{
    extern __shared__ char rawsm[];
    const uint32_t smb = smem_u32(rawsm);
    const int tid  = threadIdx.x;
    const int lane = tid & 31;
    const int wid  = tid >> 5;
    const int wm   = wid >> 2;   // 0..1
    const int wn   = wid & 3;    // 0..3

#pragma unroll
    for (int i = 0; i < 4; ++i)
#pragma unroll
        for (int j = 0; j < 4; ++j)
#pragma unroll
            for (int k = 0; k < 4; ++k) acc[i][j][k] = 0.f;

    const int nch = ktotal >> 5;

    fill_chunk(smb, Ah, Al, lda, Bh, Bl, ldb, 0, tid);
    CP_COMMIT();

    // per-lane fragment address components (fixed across chunks)
    const uint32_t a_row_off = (uint32_t)((wm * 64 + (lane & 15)) * ROWP);
    const uint32_t b_row_off = (uint32_t)((wn * 32 + (lane & 7) + ((lane >> 3) & 1) * 8) * ROWP);
    const uint32_t k_half    = (uint32_t)(((lane >> 4) & 1) * 16);

    for (int c = 0; c < nch; ++c) {
        if (c + 1 < nch) {
            fill_chunk(smb + (uint32_t)(((c + 1) & 1) * STAGE_B),
                       Ah, Al, lda, Bh, Bl, ldb, (c + 1) << 5, tid);
            CP_COMMIT();
            CP_WAIT(1);
        } else {
            CP_WAIT(0);
        }
        __syncthreads();

        const uint32_t sb = smb + (uint32_t)((c & 1) * STAGE_B);

#pragma unroll
        for (int ks = 0; ks < 2; ++ks) {
            const uint32_t ko = (uint32_t)(ks * 32) + k_half;

            uint32_t ra_h[4][4], ra_l[4][4], rb_h[2][4], rb_l[2][4];
#pragma unroll
            for (int mf = 0; mf < 4; ++mf) {
                ldm4(sb + OFF_AH + a_row_off + (uint32_t)(mf * 16 * ROWP) + ko, ra_h[mf]);
                ldm4(sb + OFF_AL + a_row_off + (uint32_t)(mf * 16 * ROWP) + ko, ra_l[mf]);
            }
#pragma unroll
            for (int bf = 0; bf < 2; ++bf) {
                ldm4(sb + OFF_BH + b_row_off + (uint32_t)(bf * 16 * ROWP) + ko, rb_h[bf]);
                ldm4(sb + OFF_BL + b_row_off + (uint32_t)(bf * 16 * ROWP) + ko, rb_l[bf]);
            }
            // pass 1: Ah*Bh  (acc frags touched once per pass -> RAW distance 16)
#pragma unroll
            for (int mf = 0; mf < 4; ++mf)
#pragma unroll
                for (int bf = 0; bf < 2; ++bf) {
                    mma16816(acc[mf][bf * 2],     ra_h[mf], rb_h[bf][0], rb_h[bf][2]);
                    mma16816(acc[mf][bf * 2 + 1], ra_h[mf], rb_h[bf][1], rb_h[bf][3]);
                }
            // pass 2: Ah*Bl
#pragma unroll
            for (int mf = 0; mf < 4; ++mf)
#pragma unroll
                for (int bf = 0; bf < 2; ++bf) {
                    mma16816(acc[mf][bf * 2],     ra_h[mf], rb_l[bf][0], rb_l[bf][2]);
                    mma16816(acc[mf][bf * 2 + 1], ra_h[mf], rb_l[bf][1], rb_l[bf][3]);
                }
            // pass 3: Al*Bh
#pragma unroll
            for (int mf = 0; mf < 4; ++mf)
#pragma unroll
                for (int bf = 0; bf < 2; ++bf) {
                    mma16816(acc[mf][bf * 2],     ra_l[mf], rb_h[bf][0], rb_h[bf][2]);
                    mma16816(acc[mf][bf * 2 + 1], ra_l[mf], rb_h[bf][1], rb_h[bf][3]);
                }
        }
        __syncthreads();
    }
}

// ---------------- stage kernels ----------------

__global__ __launch_bounds__(1024) void convert_x_kernel(const float* __restrict__ x) {
    size_t i = (size_t)blockIdx.x * blockDim.x + threadIdx.x;
    if (i >= NSD) return;
    float v = x[i];
    __nv_bfloat16 h = __float2bfloat16(v);
    g_Xh[i] = h;
    g_Xl[i] = __float2bfloat16(v - __bfloat162float(h));
}

__global__ __launch_bounds__(1024) void convert_w_kernel(const float* __restrict__ wq,
                                                         const float* __restrict__ wk,
                                                         const float* __restrict__ wv) {
    size_t i = (size_t)blockIdx.x * blockDim.x + threadIdx.x;
    if (i >= NW) return;
    size_t which = i >> 18;
    size_t off   = i & 262143ull;
    const float* src = (which == 0) ? wq : (which == 1) ? wk : wv;
    float v = src[off];
    __nv_bfloat16 h = __float2bfloat16(v);
    g_Wh[i] = h;
    g_Wl[i] = __float2bfloat16(v - __bfloat162float(h));
}

// QKV projection: grid (4 ntile, 128 mtile, 3 which)
__global__ __launch_bounds__(256, 1) void proj_kernel() {
    const int nt = blockIdx.x, mt = blockIdx.y, z = blockIdx.z;
    const __nv_bfloat16* Ah = g_Xh + (size_t)mt * 128 * DIM;
    const __nv_bfloat16* Al = g_Xl + (size_t)mt * 128 * DIM;
    const __nv_bfloat16* Bh = g_Wh + (size_t)z * DIM * DIM + (size_t)nt * 128 * DIM;
    const __nv_bfloat16* Bl = g_Wl + (size_t)z * DIM * DIM + (size_t)nt * 128 * DIM;

    float acc[4][4][4];
    gemm_bf16x3(Ah, Al, DIM, Bh, Bl, DIM, DIM, acc);

    __nv_bfloat16* Ch = (z == 0) ? g_Qh : (z == 1) ? g_Kh : g_Vh;
    __nv_bfloat16* Cl = (z == 0) ? g_Ql : (z == 1) ? g_Kl : g_Vl;

    const int lane = threadIdx.x & 31, wid = threadIdx.x >> 5;
    const int wm = wid >> 2, wn = wid & 3;
    const int g = lane >> 2, t = lane & 3;
    const size_t rbase = (size_t)mt * 128;
    const int cbase = nt * 128 + wn * 32 + 2 * t;

#pragma unroll
    for (int mf = 0; mf < 4; ++mf) {
#pragma unroll
        for (int nf = 0; nf < 4; ++nf) {
            const int col = cbase + nf * 8;
#pragma unroll
            for (int half = 0; half < 2; ++half) {
                const int row = wm * 64 + mf * 16 + g + half * 8;
                float v0 = acc[mf][nf][half * 2];
                float v1 = acc[mf][nf][half * 2 + 1];
                __nv_bfloat16 h0 = __float2bfloat16(v0);
                __nv_bfloat16 h1 = __float2bfloat16(v1);
                __nv_bfloat16 l0 = __float2bfloat16(v0 - __bfloat162float(h0));
                __nv_bfloat16 l1 = __float2bfloat16(v1 - __bfloat162float(h1));
                size_t o = (rbase + row) * DIM + col;
                *reinterpret_cast<__nv_bfloat162*>(Ch + o) = __nv_bfloat162(h0, h1);
                *reinterpret_cast<__nv_bfloat162*>(Cl + o) = __nv_bfloat162(l0, l1);
            }
        }
    }
}

// Transpose V (per batch) -> VT [D, S]
__global__ __launch_bounds__(256) void transpose_v_kernel() {
    __shared__ __nv_bfloat16 th[32][33], tl[32][33];
    const int b = blockIdx.z;
    const int d0 = blockIdx.x * 32, s0 = blockIdx.y * 32;
    const int tx = threadIdx.x, ty = threadIdx.y;
#pragma unroll
    for (int rr = ty; rr < 32; rr += 8) {
        size_t src = ((size_t)b * SEQ + s0 + rr) * DIM + d0 + tx;
        th[rr][tx] = g_Vh[src];
        tl[rr][tx] = g_Vl[src];
    }
    __syncthreads();
#pragma unroll
    for (int rr = ty; rr < 32; rr += 8) {
        size_t dst = ((size_t)b * DIM + d0 + rr) * SEQ + s0 + tx;
        g_VTh[dst] = th[tx][rr];
        g_VTl[dst] = tl[tx][rr];
    }
}

// Scores: grid (32 kt, 32 qt, 4 b), skip kt > qt
__global__ __launch_bounds__(256, 1) void scores_kernel() {
    const int kt = blockIdx.x, qt = blockIdx.y, b = blockIdx.z;
    if (kt > qt) return;

    const size_t qoff = ((size_t)b * SEQ + (size_t)qt * 128) * DIM;
    const size_t koff = ((size_t)b * SEQ + (size_t)kt * 128) * DIM;

    float acc[4][4][4];
    gemm_bf16x3(g_Qh + qoff, g_Ql + qoff, DIM,
                g_Kh + koff, g_Kl + koff, DIM, DIM, acc);

    const int lane = threadIdx.x & 31, wid = threadIdx.x >> 5;
    const int wm = wid >> 2, wn = wid & 3;
    const int g = lane >> 2, t = lane & 3;
    const float scale = 0.04419417382415922f;   // 1/sqrt(512)

#pragma unroll
    for (int mf = 0; mf < 4; ++mf) {
#pragma unroll
        for (int nf = 0; nf < 4; ++nf) {
            const int col = kt * 128 + wn * 32 + nf * 8 + 2 * t;
#pragma unroll
            for (int half = 0; half < 2; ++half) {
                const int qrow = qt * 128 + wm * 64 + mf * 16 + g + half * 8;
                float v0 = (col     <= qrow) ? acc[mf][nf][half * 2]     * scale : -1e30f;
                float v1 = (col + 1 <= qrow) ? acc[mf][nf][half * 2 + 1] * scale : -1e30f;
                float* dst = g_P + ((size_t)b * SEQ + qrow) * SEQ + col;
                *reinterpret_cast<float2*>(dst) = make_float2(v0, v1);
            }
        }
    }
}

// Row softmax over [0, jend), writes normalized probs as bf16 hi/lo
__global__ __launch_bounds__(256) void softmax_kernel() {
    const int rr = blockIdx.x;
    const int b = rr >> 12;
    const int i = rr & 4095;
    const size_t rowoff = ((size_t)b * SEQ + i) * SEQ;
    const float* row = g_P + rowoff;
    const int jend = ((i >> 7) + 1) << 7;

    const int tid = threadIdx.x, lane = tid & 31, wid = tid >> 5;
    __shared__ float red[8];

    float m = -1e30f;
    for (int j = tid; j < jend; j += 256) m = fmaxf(m, row[j]);
#pragma unroll
    for (int o = 16; o > 0; o >>= 1) m = fmaxf(m, __shfl_xor_sync(0xffffffffu, m, o));
    if (lane == 0) red[wid] = m;
    __syncthreads();
    m = red[0];
#pragma unroll
    for (int w = 1; w < 8; w++) m = fmaxf(m, red[w]);
    __syncthreads();

    float s = 0.f;
    for (int j = tid; j < jend; j += 256) s += expf(row[j] - m);
#pragma unroll
    for (int o = 16; o > 0; o >>= 1) s += __shfl_xor_sync(0xffffffffu, s, o);
    if (lane == 0) red[wid] = s;
    __syncthreads();
    s = red[0];
#pragma unroll
    for (int w = 1; w < 8; w++) s += red[w];

    const float inv = 1.0f / s;
    for (int j = tid; j < jend; j += 256) {
        float e = expf(row[j] - m) * inv;
        __nv_bfloat16 h = __float2bfloat16(e);
        g_Ph[rowoff + j] = h;
        g_Pl[rowoff + j] = __float2bfloat16(e - __bfloat162float(h));
    }
}

// PV: grid (4 ntile, 32 qt, 4 b), K bounded by causal extent
__global__ __launch_bounds__(256, 1) void pv_kernel(float* __restrict__ out) {
    const int nt = blockIdx.x, qt = blockIdx.y, b = blockIdx.z;

    const size_t poff = ((size_t)b * SEQ + (size_t)qt * 128) * SEQ;
    const size_t voff = ((size_t)b * DIM + (size_t)nt * 128) * SEQ;
    const int kmax = (qt + 1) * 128;

    float acc[4][4][4];
    gemm_bf16x3(g_Ph + poff, g_Pl + poff, SEQ,
                g_VTh + voff, g_VTl + voff, SEQ, kmax, acc);

    const int lane = threadIdx.x & 31, wid = threadIdx.x >> 5;
    const int wm = wid >> 2, wn = wid & 3;
    const int g = lane >> 2, t = lane & 3;

#pragma unroll
    for (int mf = 0; mf < 4; ++mf) {
#pragma unroll
        for (int nf = 0; nf < 4; ++nf) {
            const int col = nt * 128 + wn * 32 + nf * 8 + 2 * t;
#pragma unroll
            for (int half = 0; half < 2; ++half) {
                const int row = qt * 128 + wm * 64 + mf * 16 + g + half * 8;
                float* dst = out + ((size_t)b * SEQ + row) * DIM + col;
                *reinterpret_cast<float2*>(dst) =
                    make_float2(acc[mf][nf][half * 2], acc[mf][nf][half * 2 + 1]);
            }
        }
    }
}

// ---------------- launch ----------------
extern "C" void kernel_launch(void* const* d_in, const int* in_sizes, int n_in,
                              void* d_out, int out_size)
{
    const float* x  = (const float*)d_in[0];
    const float* WQ = (const float*)d_in[1];
    const float* WK = (const float*)d_in[2];
    const float* WV = (const float*)d_in[3];
    float* out = (float*)d_out;

    cudaFuncSetAttribute(proj_kernel,   cudaFuncAttributeMaxDynamicSharedMemorySize, SMEM_ALLOC);
    cudaFuncSetAttribute(scores_kernel, cudaFuncAttributeMaxDynamicSharedMemorySize, SMEM_ALLOC);
    cudaFuncSetAttribute(pv_kernel,     cudaFuncAttributeMaxDynamicSharedMemorySize, SMEM_ALLOC);

    convert_x_kernel<<<8192, 1024>>>(x);
    convert_w_kernel<<<768, 1024>>>(WQ, WK, WV);

    proj_kernel<<<dim3(4, 128, 3), 256, SMEM_ALLOC>>>();

    transpose_v_kernel<<<dim3(16, 128, 4), dim3(32, 8)>>>();

    scores_kernel<<<dim3(32, 32, 4), 256, SMEM_ALLOC>>>();

    softmax_kernel<<<BATCH * SEQ, 256>>>();

    pv_kernel<<<dim3(4, 32, 4), 256, SMEM_ALLOC>>>(out);
}